// round 16
// baseline (speedup 1.0000x reference)
#include <cuda_runtime.h>
#include <cuda_fp16.h>
#include <stdint.h>

// Problem constants
#define NB 2
#define LL 1024
#define HH 16
#define DD 128
// SCALE = 1/sqrt(2048); QSCALE = SCALE * log2(e) folded into q projection
#define QSCALE 0.03187936005f

// Scratch (device statics; no allocations allowed)
__device__ __half g_q[NB*LL*HH*DD];
__device__ __half g_k[NB*LL*HH*DD];
__device__ __half g_v[NB*LL*HH*DD];
__device__ __half g_o[NB*LL*HH*DD];   // attention output (n,l,h,d)
__device__ __half g_woh[2048*2048];   // Wo converted to half
__device__ uint2  g_mp[NB*16*LL];     // packed mask bits: [n][ktile16][q], 64 bits
__device__ float  g_cos[LL*64];
__device__ float  g_sin[LL*64];
__device__ int    g_sync[16];         // per-row-block completion counters

// ---------------------------------------------------------------------------
// Common helpers
// ---------------------------------------------------------------------------
__device__ __forceinline__ uint32_t smem_u32(const void* p) {
    uint32_t a;
    asm("{ .reg .u64 t; cvta.to.shared.u64 t, %1; cvt.u32.u64 %0, t; }"
        : "=r"(a) : "l"(p));
    return a;
}
__device__ __forceinline__ void cp16(uint32_t s, const __half* g) {
    asm volatile("cp.async.ca.shared.global [%0], [%1], 16;"
                 :: "r"(s), "l"(__cvta_generic_to_global(g)));
}
#define CP_COMMIT() asm volatile("cp.async.commit_group;" ::: "memory")
#define CP_WAIT1()  asm volatile("cp.async.wait_group 1;" ::: "memory")
#define CP_WAIT2()  asm volatile("cp.async.wait_group 2;" ::: "memory")

__device__ __forceinline__ uint4 pack8(float4 a, float4 b) {
    __half2 h0 = __floats2half2_rn(a.x, a.y);
    __half2 h1 = __floats2half2_rn(a.z, a.w);
    __half2 h2 = __floats2half2_rn(b.x, b.y);
    __half2 h3 = __floats2half2_rn(b.z, b.w);
    uint4 u;
    u.x = *reinterpret_cast<uint32_t*>(&h0);
    u.y = *reinterpret_cast<uint32_t*>(&h1);
    u.z = *reinterpret_cast<uint32_t*>(&h2);
    u.w = *reinterpret_cast<uint32_t*>(&h3);
    return u;
}
__device__ __forceinline__ uint32_t packh2(float x, float y) {
    __half2 h = __floats2half2_rn(x, y);
    return *reinterpret_cast<uint32_t*>(&h);
}
__device__ __forceinline__ float ex2f(float x) {
    float r;
    asm("ex2.approx.ftz.f32 %0, %1;" : "=f"(r) : "f"(x));
    return r;
}

__device__ __forceinline__ void mma16(float* d, const uint32_t* a, const uint32_t* b) {
    asm volatile(
        "mma.sync.aligned.m16n8k16.row.col.f32.f16.f16.f32 "
        "{%0,%1,%2,%3}, {%4,%5,%6,%7}, {%8,%9}, {%0,%1,%2,%3};"
        : "+f"(d[0]), "+f"(d[1]), "+f"(d[2]), "+f"(d[3])
        : "r"(a[0]), "r"(a[1]), "r"(a[2]), "r"(a[3]), "r"(b[0]), "r"(b[1]));
}
__device__ __forceinline__ void ldsm_x4(uint32_t* r, uint32_t addr) {
    asm volatile("ldmatrix.sync.aligned.m8n8.x4.shared.b16 {%0,%1,%2,%3}, [%4];"
                 : "=r"(r[0]), "=r"(r[1]), "=r"(r[2]), "=r"(r[3]) : "r"(addr));
}
__device__ __forceinline__ void ldsm_x4t(uint32_t* r, uint32_t addr) {
    asm volatile("ldmatrix.sync.aligned.m8n8.x4.trans.shared.b16 {%0,%1,%2,%3}, [%4];"
                 : "=r"(r[0]), "=r"(r[1]), "=r"(r[2]), "=r"(r[3]) : "r"(addr));
}

// ---------------------------------------------------------------------------
// ldmatrix-based k16 step (64x32 warp tile), row stride RST halves.
// A rows wr*64.., B cols wc*32.. (both K-major).
// ---------------------------------------------------------------------------
template<int RST>
__device__ __forceinline__ void mma_k16_ldsm(uint32_t As, uint32_t Bs, int ks,
                                             float d[4][4][4], int lane,
                                             int wr, int wc)
{
    int ar = lane & 15, ak = (lane >> 4) << 3;
    int brw = ((lane >> 4) << 3) + (lane & 7);
    int bk = ((lane >> 3) & 1) << 3;
    uint32_t a[4][4];
    #pragma unroll
    for (int mt = 0; mt < 4; mt++)
        ldsm_x4(a[mt], As + (uint32_t)((wr*64 + mt*16 + ar)*RST + ks*16 + ak)*2);
    #pragma unroll
    for (int g = 0; g < 2; g++) {
        uint32_t b[4];
        ldsm_x4(b, Bs + (uint32_t)((wc*32 + g*16 + brw)*RST + ks*16 + bk)*2);
        #pragma unroll
        for (int mt = 0; mt < 4; mt++) {
            mma16(d[mt][2*g],   a[mt], b);
            mma16(d[mt][2*g+1], a[mt], b + 2);
        }
    }
}

// ---------------------------------------------------------------------------
// proj / out-role tile constants (BK=32, row stride 40 halves)
// ---------------------------------------------------------------------------
#define ST 40
#define TILE_H (128*ST)
#define STAGES 3
#define OUT_SMEM_H (STAGES*2*TILE_H)     // out role: 61440 B of the merged smem

// 256-thread loader for a 128x32-half tile
__device__ __forceinline__ void cp_tile(uint32_t sb, const __half* __restrict__ g,
                                        int stride, int tid) {
    #pragma unroll
    for (int t = 0; t < 2; t++) {
        int i = tid + t*256;
        int r = i >> 2, c = i & 3;
        cp16(sb + r*80 + c*16, g + (size_t)r*stride + c*8);
    }
}

// ---------------------------------------------------------------------------
// flash constants
// ---------------------------------------------------------------------------
#define FST 136
#define QTILE (128*FST)
#define KTILE (64*FST)
#define FO_BYTES ((QTILE + 4*KTILE)*2)   // 104448 (covers out role's 61440 too)

__device__ __forceinline__ void cp_ftileQ(uint32_t sb, const __half* __restrict__ g,
                                          int stride, int tid) {
    #pragma unroll
    for (int j = 0; j < 8; j++) {
        int id = tid + j*256;
        int r = id >> 4, c = id & 15;
        cp16(sb + (r*FST + c*8)*2, g + (size_t)r*stride + c*8);
    }
}
__device__ __forceinline__ void cp_ftile64(uint32_t sb, const __half* __restrict__ g,
                                           int stride, int tid) {
    #pragma unroll
    for (int j = 0; j < 4; j++) {
        int id = tid + j*256;
        int r = id >> 4, c = id & 15;
        cp16(sb + (r*FST + c*8)*2, g + (size_t)r*stride + c*8);
    }
}

// ---------------------------------------------------------------------------
// K0: prelude — RoPE table + Wo->half + mask bit-pack + counter zero.
// ---------------------------------------------------------------------------
__global__ __launch_bounds__(256) void prelude_kernel(
    const float* __restrict__ Wo, const int* __restrict__ mask)
{
    int b = blockIdx.x, tid = threadIdx.x;
    if (b == 0 && tid < 16) g_sync[tid] = 0;
    {
        int i = (b*256 + tid) * 8;
        float4 a = *reinterpret_cast<const float4*>(Wo + i);
        float4 c = *reinterpret_cast<const float4*>(Wo + i + 4);
        *reinterpret_cast<uint4*>(g_woh + i) = pack8(a, c);
    }
    if (b < 1024 && tid < 64) {
        float expo = (float)(2 * tid) / 128.0f;
        float invf = 1.0f / powf(10000.0f, expo);
        float a = (float)b * invf;
        g_cos[b*64 + tid] = cosf(a);
        g_sin[b*64 + tid] = sinf(a);
    }
    if (b >= 1024 && b < 1152) {
        int w = (b - 1024)*256 + tid;
        int n = w >> 14, rem = w & 16383;
        int t = rem >> 10, q = rem & 1023;
        const int* mr = mask + ((size_t)n << 20) + q*1024 + t*64;
        uint32_t lo = 0, hi = 0;
        #pragma unroll
        for (int i4 = 0; i4 < 8; i4++) {
            int4 m = reinterpret_cast<const int4*>(mr)[i4];
            lo |= (uint32_t)(m.x != 0) << (i4*4 + 0);
            lo |= (uint32_t)(m.y != 0) << (i4*4 + 1);
            lo |= (uint32_t)(m.z != 0) << (i4*4 + 2);
            lo |= (uint32_t)(m.w != 0) << (i4*4 + 3);
        }
        #pragma unroll
        for (int i4 = 8; i4 < 16; i4++) {
            int4 m = reinterpret_cast<const int4*>(mr)[i4];
            hi |= (uint32_t)(m.x != 0) << ((i4-8)*4 + 0);
            hi |= (uint32_t)(m.y != 0) << ((i4-8)*4 + 1);
            hi |= (uint32_t)(m.z != 0) << ((i4-8)*4 + 2);
            hi |= (uint32_t)(m.w != 0) << ((i4-8)*4 + 3);
        }
        g_mp[(n*16 + t)*1024 + q] = make_uint2(lo, hi);
    }
}

// ---------------------------------------------------------------------------
// K1: fused RoPE + per-head projection (R12 config). grid (256, 3), 256 thr.
// ---------------------------------------------------------------------------
__device__ __forceinline__ void ldgf(float4 v[4], const float* __restrict__ g,
                                     int stride, int tid) {
    #pragma unroll
    for (int t = 0; t < 2; t++) {
        int i = tid + t*256;
        int r = i >> 2, k8 = (i & 3) << 3;
        v[2*t]   = *reinterpret_cast<const float4*>(g + (size_t)r*stride + k8);
        v[2*t+1] = *reinterpret_cast<const float4*>(g + (size_t)r*stride + k8 + 4);
    }
}
__device__ __forceinline__ void stsf(__half* S, const float4 v[4], int tid) {
    #pragma unroll
    for (int t = 0; t < 2; t++) {
        int i = tid + t*256;
        int r = i >> 2, k8 = (i & 3) << 3;
        *reinterpret_cast<uint4*>(S + r*ST + k8) = pack8(v[2*t], v[2*t+1]);
    }
}
__device__ __forceinline__ void ldg_rope(float4 v[4], const float* __restrict__ X,
                                         int base, int k0, int tid) {
    #pragma unroll
    for (int t = 0; t < 2; t++) {
        int i = tid + t*256;
        int r = i >> 2, k8 = (i & 3) << 3;
        int rg = base + r;
        int l = (rg >> 4) & 1023;
        const float* xr = X + (size_t)rg*128;
        #pragma unroll
        for (int hlf = 0; hlf < 2; hlf++) {
            int dd = k0 + k8 + hlf*4;
            float4 f = *reinterpret_cast<const float4*>(xr + dd);
            float4 m = *reinterpret_cast<const float4*>(xr + 124 - dd);
            float4 c = *reinterpret_cast<const float4*>(g_cos + l*64 + (dd & 63));
            float4 s = *reinterpret_cast<const float4*>(g_sin + l*64 + (dd & 63));
            v[2*t+hlf] = make_float4(f.x*c.x + m.w*s.x, f.y*c.y + m.z*s.y,
                                     f.z*c.z + m.y*s.z, f.w*c.w + m.x*s.w);
        }
    }
}

__global__ __launch_bounds__(256, 2) void proj_kernel(
    const float* __restrict__ qin, const float* __restrict__ kin,
    const float* __restrict__ vin,
    const float* __restrict__ Wq, const float* __restrict__ Wk,
    const float* __restrict__ Wv)
{
    __shared__ __half sm[4*TILE_H];
    __half *A0 = sm, *A1 = sm + TILE_H, *B0 = sm + 2*TILE_H, *B1 = sm + 3*TILE_H;
    uint32_t smb = smem_u32(sm);
    int tid = threadIdx.x;
    int lane = tid & 31, wid = tid >> 5;
    int tr = lane >> 2, tk = lane & 3;
    int wr = wid >> 2, wc = wid & 3;
    int tensor = blockIdx.y;
    const float* X = (tensor == 0) ? qin : (tensor == 1) ? kin : vin;
    const float* W = (tensor == 0) ? Wq  : (tensor == 1) ? Wk  : Wv;
    __half* OUT    = (tensor == 0) ? g_q : (tensor == 1) ? g_k : g_v;
    bool rope = (tensor < 2);
    float osc = (tensor == 0) ? QSCALE : 1.0f;
    int base = blockIdx.x * 128;

    float d[4][4][4] = {};
    float4 va[4], vb[4];

    if (rope) ldg_rope(va, X, base, 0, tid);
    else      ldgf(va, X + (size_t)base*128, 128, tid);
    ldgf(vb, W, 128, tid);
    stsf(A0, va, tid); stsf(B0, vb, tid);
    __syncthreads();

    #pragma unroll
    for (int t = 0; t < 4; t++) {
        if (t < 3) {
            int k0 = (t+1)*32;
            if (rope) ldg_rope(va, X, base, k0, tid);
            else      ldgf(va, X + (size_t)base*128 + k0, 128, tid);
            ldgf(vb, W + k0, 128, tid);
        }
        uint32_t Asa = smb + (uint32_t)(((t & 1) ? TILE_H : 0))*2;
        uint32_t Bsa = smb + (uint32_t)((2 + (t & 1))*TILE_H)*2;
        mma_k16_ldsm<ST>(Asa, Bsa, 0, d, lane, wr, wc);
        mma_k16_ldsm<ST>(Asa, Bsa, 1, d, lane, wr, wc);
        if (t < 3) {
            stsf((t & 1) ? A0 : A1, va, tid);
            stsf((t & 1) ? B0 : B1, vb, tid);
        }
        __syncthreads();
    }

    #pragma unroll
    for (int mt = 0; mt < 4; mt++) {
        int rg = base + wr*64 + mt*16 + tr;
        #pragma unroll
        for (int nt = 0; nt < 4; nt++) {
            int col = wc*32 + nt*8 + tk*2;
            *reinterpret_cast<uint32_t*>(&OUT[(size_t)rg*128 + col]) =
                packh2(d[mt][nt][0]*osc, d[mt][nt][1]*osc);
            *reinterpret_cast<uint32_t*>(&OUT[(size_t)(rg+8)*128 + col]) =
                packh2(d[mt][nt][2]*osc, d[mt][nt][3]*osc);
        }
    }
}

// ---------------------------------------------------------------------------
// K2: MERGED flash + out. grid 512 x 256 thr, 104448 B smem, 2 CTAs/SM.
// bids 0..255: flash (producer, signals g_sync[rowblk] per q-block).
// bids 256..511: out (consumer, waits for its row-block's 16 heads).
// Deadlock-free: 256 out CTAs < 296 slots => flash always has residency.
// ---------------------------------------------------------------------------
__global__ __launch_bounds__(256, 2) void fo_kernel(
    const float* __restrict__ bo, float* __restrict__ out)
{
    extern __shared__ __half dsm[];
    int tid = threadIdx.x;
    int lane = tid & 31, wid = tid >> 5;
    int tr = lane >> 2, tk = lane & 3;
    int bid = blockIdx.x;

    if (bid < 256) {
        // ================= FLASH role =================
        int q0i = bid & 7, nh = bid >> 3;
        int n = nh >> 4, h = nh & 15;
        int q0 = q0i * 128;
        int w16 = wid * 16;

        uint32_t qb = smem_u32(dsm);
        uint32_t kb[2] = {(uint32_t)(qb + QTILE*2), (uint32_t)(qb + (QTILE + KTILE)*2)};
        uint32_t vb[2] = {(uint32_t)(qb + (QTILE + 2*KTILE)*2),
                          (uint32_t)(qb + (QTILE + 3*KTILE)*2)};

        const __half* Kg = g_k + ((size_t)n*LL*HH + h)*DD;
        const __half* Vg = g_v + ((size_t)n*LL*HH + h)*DD;

        cp_ftileQ(qb, g_q + ((size_t)(n*LL + q0)*HH + h)*DD, HH*DD, tid);
        cp_ftile64(kb[0], Kg, HH*DD, tid);
        CP_COMMIT();
        cp_ftile64(vb[0], Vg, HH*DD, tid);
        CP_COMMIT();
        cp_ftile64(kb[1], Kg + (size_t)64*HH*DD, HH*DD, tid);
        CP_COMMIT();

        uint32_t a_off = ((uint32_t)((w16 + (lane & 15))*FST + ((lane >> 4) << 3))) * 2;
        int b_row = ((lane >> 4) << 3) + (lane & 7);
        int b_koff = ((lane >> 3) & 1) << 3;
        int v_row = (((lane >> 3) & 1) << 3) + (lane & 7);
        int v_coff = (lane >> 4) << 3;

        float o[16][4] = {};
        float l0 = 0.0f, l1 = 0.0f;
        int q_r0 = q0 + w16 + tr;
        int tk2 = tk*2;

        for (int t = 0; t < 16; t++) {
            CP_WAIT2();
            __syncthreads();

            float d[8][4] = {};
            uint32_t kbase = kb[t & 1];
            #pragma unroll
            for (int ks = 0; ks < 8; ks++) {
                uint32_t a[4];
                ldsm_x4(a, qb + a_off + ks*32);
                #pragma unroll
                for (int ntp = 0; ntp < 4; ntp++) {
                    uint32_t b[4];
                    ldsm_x4(b, kbase + ((uint32_t)((ntp*16 + b_row)*FST + ks*16 + b_koff))*2);
                    mma16(d[2*ntp],   a, b);
                    mma16(d[2*ntp+1], a, b + 2);
                }
            }

            uint2 wq0 = g_mp[(n*16 + t)*1024 + q_r0];
            uint2 wq1 = g_mp[(n*16 + t)*1024 + q_r0 + 8];
            uint32_t l0b = wq0.x >> tk2, h0b = wq0.y >> tk2;
            uint32_t l1b = wq1.x >> tk2, h1b = wq1.y >> tk2;

            float rs0 = 0.0f, rs1 = 0.0f;
            #pragma unroll
            for (int nt = 0; nt < 8; nt++) {
                uint32_t b0 = ((nt < 4) ? l0b : h0b) >> ((nt & 3)*8);
                uint32_t b1 = ((nt < 4) ? l1b : h1b) >> ((nt & 3)*8);
                float e0 = ex2f(d[nt][0]);
                float e1 = ex2f(d[nt][1]);
                float e2 = ex2f(d[nt][2]);
                float e3 = ex2f(d[nt][3]);
                d[nt][0] = (b0 & 1u) ? e0 : 0.0f;
                d[nt][1] = (b0 & 2u) ? e1 : 0.0f;
                d[nt][2] = (b1 & 1u) ? e2 : 0.0f;
                d[nt][3] = (b1 & 2u) ? e3 : 0.0f;
                rs0 += d[nt][0] + d[nt][1];
                rs1 += d[nt][2] + d[nt][3];
            }
            l0 += rs0;
            l1 += rs1;

            CP_WAIT1();
            __syncthreads();
            if (t < 15) cp_ftile64(vb[(t+1) & 1], Vg + (size_t)(t+1)*64*HH*DD, HH*DD, tid);
            CP_COMMIT();
            if (t < 14) cp_ftile64(kb[t & 1], Kg + (size_t)(t+2)*64*HH*DD, HH*DD, tid);
            CP_COMMIT();

            uint32_t vbase = vb[t & 1];
            #pragma unroll
            for (int ks = 0; ks < 4; ks++) {
                uint32_t a[4];
                a[0] = packh2(d[2*ks][0],   d[2*ks][1]);
                a[1] = packh2(d[2*ks][2],   d[2*ks][3]);
                a[2] = packh2(d[2*ks+1][0], d[2*ks+1][1]);
                a[3] = packh2(d[2*ks+1][2], d[2*ks+1][3]);
                #pragma unroll
                for (int ntp = 0; ntp < 8; ntp++) {
                    uint32_t b[4];
                    ldsm_x4t(b, vbase + ((uint32_t)((ks*16 + v_row)*FST + ntp*16 + v_coff))*2);
                    mma16(o[2*ntp],   a, b);
                    mma16(o[2*ntp+1], a, b + 2);
                }
            }
        }

        l0 += __shfl_xor_sync(0xffffffffu, l0, 1);
        l0 += __shfl_xor_sync(0xffffffffu, l0, 2);
        l1 += __shfl_xor_sync(0xffffffffu, l1, 1);
        l1 += __shfl_xor_sync(0xffffffffu, l1, 2);
        float inv0 = 1.0f / l0, inv1 = 1.0f / l1;

        #pragma unroll
        for (int nt = 0; nt < 16; nt++) {
            int col = nt*8 + tk*2;
            *reinterpret_cast<uint32_t*>(&g_o[((size_t)(n*LL + q_r0)*HH + h)*DD + col]) =
                packh2(o[nt][0]*inv0, o[nt][1]*inv0);
            *reinterpret_cast<uint32_t*>(&g_o[((size_t)(n*LL + q_r0 + 8)*HH + h)*DD + col]) =
                packh2(o[nt][2]*inv1, o[nt][3]*inv1);
        }

        // release: all stores visible, then signal this (n, q-block)
        __threadfence();
        __syncthreads();
        if (tid == 0) atomicAdd(&g_sync[n*8 + q0i], 1);
    } else {
        // ================= OUT role =================
        int ob = bid - 256;
        int c0 = (ob & 15) * 128;
        int r0 = (ob >> 4) * 128;
        int rowblk = ob >> 4;

        // acquire: wait until all 16 head-tiles of this row block are in g_o
        if (tid == 0) {
            while (atomicAdd(&g_sync[rowblk], 0) < 16) __nanosleep(128);
        }
        __syncthreads();
        __threadfence();

        int wr = wid >> 2, wc = wid & 3;
        const __half* Ag = g_o + (size_t)r0*2048;
        const __half* Bg = g_woh + (size_t)c0*2048;

        float d[4][4][4] = {};
        uint32_t sb = smem_u32(dsm);

        cp_tile(sb,               Ag,      2048, tid);
        cp_tile(sb + TILE_H*2,    Bg,      2048, tid);
        CP_COMMIT();
        cp_tile(sb + 2*TILE_H*2,  Ag + 32, 2048, tid);
        cp_tile(sb + 3*TILE_H*2,  Bg + 32, 2048, tid);
        CP_COMMIT();

        for (int t = 0; t < 64; t++) {
            CP_WAIT1();
            __syncthreads();
            if (t + 2 < 64) {
                int s = (t + 2) % STAGES;
                cp_tile(sb + (uint32_t)(2*s)*TILE_H*2,   Ag + (t+2)*32, 2048, tid);
                cp_tile(sb + (uint32_t)(2*s+1)*TILE_H*2, Bg + (t+2)*32, 2048, tid);
            }
            CP_COMMIT();
            uint32_t Asa = sb + (uint32_t)((t % STAGES)*2*TILE_H)*2;
            uint32_t Bsa = Asa + TILE_H*2;
            mma_k16_ldsm<ST>(Asa, Bsa, 0, d, lane, wr, wc);
            mma_k16_ldsm<ST>(Asa, Bsa, 1, d, lane, wr, wc);
        }

        #pragma unroll
        for (int mt = 0; mt < 4; mt++) {
            int r = r0 + wr*64 + mt*16 + tr;
            #pragma unroll
            for (int nt = 0; nt < 4; nt++) {
                int col = c0 + wc*32 + nt*8 + tk*2;
                float2 bb = *reinterpret_cast<const float2*>(&bo[col]);
                *reinterpret_cast<float2*>(&out[(size_t)r*2048 + col]) =
                    make_float2(d[mt][nt][0] + bb.x, d[mt][nt][1] + bb.y);
                *reinterpret_cast<float2*>(&out[(size_t)(r+8)*2048 + col]) =
                    make_float2(d[mt][nt][2] + bb.x, d[mt][nt][3] + bb.y);
            }
        }
    }
}

// ---------------------------------------------------------------------------
// Launch: values, keys, queries, mask, Wv, Wk, Wq, Wo, bo
// ---------------------------------------------------------------------------
extern "C" void kernel_launch(void* const* d_in, const int* in_sizes, int n_in,
                              void* d_out, int out_size)
{
    const float* values  = (const float*)d_in[0];
    const float* keys    = (const float*)d_in[1];
    const float* queries = (const float*)d_in[2];
    const int*   mask    = (const int*)  d_in[3];
    const float* Wv      = (const float*)d_in[4];
    const float* Wk      = (const float*)d_in[5];
    const float* Wq      = (const float*)d_in[6];
    const float* Wo      = (const float*)d_in[7];
    const float* bo      = (const float*)d_in[8];
    float* out = (float*)d_out;

    cudaFuncSetAttribute(fo_kernel, cudaFuncAttributeMaxDynamicSharedMemorySize, FO_BYTES);

    prelude_kernel<<<2048, 256>>>(Wo, mask);
    proj_kernel<<<dim3(256, 3), 256>>>(queries, keys, values, Wq, Wk, Wv);
    fo_kernel<<<512, 256, FO_BYTES>>>(bo, out);
}

// round 17
// speedup vs baseline: 1.0918x; 1.0918x over previous
#include <cuda_runtime.h>
#include <cuda_fp16.h>
#include <stdint.h>

// Problem constants
#define NB 2
#define LL 1024
#define HH 16
#define DD 128
// SCALE = 1/sqrt(2048); QSCALE = SCALE * log2(e) folded into q projection
#define QSCALE 0.03187936005f

// Scratch (device statics; no allocations allowed)
__device__ __half g_q[NB*LL*HH*DD];
__device__ __half g_k[NB*LL*HH*DD];
__device__ __half g_v[NB*LL*HH*DD];
__device__ __half g_o[NB*LL*HH*DD];   // attention output (n,l,h,d)
__device__ __half g_woh[2048*2048];   // Wo converted to half
__device__ uint2  g_mp[NB*16*LL];     // packed mask bits: [n][ktile16][q], 64 bits
__device__ float  g_cos[LL*64];
__device__ float  g_sin[LL*64];

// ---------------------------------------------------------------------------
// Common helpers
// ---------------------------------------------------------------------------
__device__ __forceinline__ uint32_t smem_u32(const void* p) {
    uint32_t a;
    asm("{ .reg .u64 t; cvta.to.shared.u64 t, %1; cvt.u32.u64 %0, t; }"
        : "=r"(a) : "l"(p));
    return a;
}
__device__ __forceinline__ void cp16(uint32_t s, const __half* g) {
    asm volatile("cp.async.ca.shared.global [%0], [%1], 16;"
                 :: "r"(s), "l"(__cvta_generic_to_global(g)));
}
#define CP_COMMIT() asm volatile("cp.async.commit_group;" ::: "memory")
#define CP_WAIT1()  asm volatile("cp.async.wait_group 1;" ::: "memory")
#define CP_WAIT2()  asm volatile("cp.async.wait_group 2;" ::: "memory")

__device__ __forceinline__ uint4 pack8(float4 a, float4 b) {
    __half2 h0 = __floats2half2_rn(a.x, a.y);
    __half2 h1 = __floats2half2_rn(a.z, a.w);
    __half2 h2 = __floats2half2_rn(b.x, b.y);
    __half2 h3 = __floats2half2_rn(b.z, b.w);
    uint4 u;
    u.x = *reinterpret_cast<uint32_t*>(&h0);
    u.y = *reinterpret_cast<uint32_t*>(&h1);
    u.z = *reinterpret_cast<uint32_t*>(&h2);
    u.w = *reinterpret_cast<uint32_t*>(&h3);
    return u;
}
__device__ __forceinline__ uint32_t packh2(float x, float y) {
    __half2 h = __floats2half2_rn(x, y);
    return *reinterpret_cast<uint32_t*>(&h);
}
__device__ __forceinline__ float ex2f(float x) {
    float r;
    asm("ex2.approx.ftz.f32 %0, %1;" : "=f"(r) : "f"(x));
    return r;
}

__device__ __forceinline__ void mma16(float* d, const uint32_t* a, const uint32_t* b) {
    asm volatile(
        "mma.sync.aligned.m16n8k16.row.col.f32.f16.f16.f32 "
        "{%0,%1,%2,%3}, {%4,%5,%6,%7}, {%8,%9}, {%0,%1,%2,%3};"
        : "+f"(d[0]), "+f"(d[1]), "+f"(d[2]), "+f"(d[3])
        : "r"(a[0]), "r"(a[1]), "r"(a[2]), "r"(a[3]), "r"(b[0]), "r"(b[1]));
}
__device__ __forceinline__ void ldsm_x4(uint32_t* r, uint32_t addr) {
    asm volatile("ldmatrix.sync.aligned.m8n8.x4.shared.b16 {%0,%1,%2,%3}, [%4];"
                 : "=r"(r[0]), "=r"(r[1]), "=r"(r[2]), "=r"(r[3]) : "r"(addr));
}
__device__ __forceinline__ void ldsm_x4t(uint32_t* r, uint32_t addr) {
    asm volatile("ldmatrix.sync.aligned.m8n8.x4.trans.shared.b16 {%0,%1,%2,%3}, [%4];"
                 : "=r"(r[0]), "=r"(r[1]), "=r"(r[2]), "=r"(r[3]) : "r"(addr));
}

// ---------------------------------------------------------------------------
// ldmatrix-based k16 step (64x32 warp tile), row stride RST halves.
// A rows wr*64.., B cols wc*32.. (both K-major).
// ---------------------------------------------------------------------------
template<int RST>
__device__ __forceinline__ void mma_k16_ldsm(uint32_t As, uint32_t Bs, int ks,
                                             float d[4][4][4], int lane,
                                             int wr, int wc)
{
    int ar = lane & 15, ak = (lane >> 4) << 3;
    int brw = ((lane >> 4) << 3) + (lane & 7);
    int bk = ((lane >> 3) & 1) << 3;
    uint32_t a[4][4];
    #pragma unroll
    for (int mt = 0; mt < 4; mt++)
        ldsm_x4(a[mt], As + (uint32_t)((wr*64 + mt*16 + ar)*RST + ks*16 + ak)*2);
    #pragma unroll
    for (int g = 0; g < 2; g++) {
        uint32_t b[4];
        ldsm_x4(b, Bs + (uint32_t)((wc*32 + g*16 + brw)*RST + ks*16 + bk)*2);
        #pragma unroll
        for (int mt = 0; mt < 4; mt++) {
            mma16(d[mt][2*g],   a[mt], b);
            mma16(d[mt][2*g+1], a[mt], b + 2);
        }
    }
}

// ---------------------------------------------------------------------------
// proj path constants (BK=32 tiles, static smem, reg-staged RoPE loader)
// ---------------------------------------------------------------------------
#define ST 40
#define TILE_H (128*ST)

// ---------------------------------------------------------------------------
// out path constants (BK=64, 3-stage ring, 128 threads, 64x64 warp tiles)
// ---------------------------------------------------------------------------
#define ST2 72
#define TILE64_H (128*ST2)
#define STAGES 3
#define OUT_BYTES (STAGES*2*TILE64_H*2)   // 110592

// 128-thread loader for a 128x64 tile
__device__ __forceinline__ void cp_tile64(uint32_t sb, const __half* __restrict__ g,
                                          int stride, int tid) {
    #pragma unroll
    for (int t = 0; t < 8; t++) {
        int i = tid + t*128;
        int r = i >> 3, c = i & 7;
        cp16(sb + (r*ST2 + c*8)*2, g + (size_t)r*stride + c*8);
    }
}

// ---------------------------------------------------------------------------
// K0: prelude — RoPE table + Wo->half + mask bit-pack, one launch. grid 2048.
// ---------------------------------------------------------------------------
__global__ __launch_bounds__(256) void prelude_kernel(
    const float* __restrict__ Wo, const int* __restrict__ mask)
{
    int b = blockIdx.x, tid = threadIdx.x;
    {
        int i = (b*256 + tid) * 8;
        float4 a = *reinterpret_cast<const float4*>(Wo + i);
        float4 c = *reinterpret_cast<const float4*>(Wo + i + 4);
        *reinterpret_cast<uint4*>(g_woh + i) = pack8(a, c);
    }
    if (b < 1024 && tid < 64) {
        float expo = (float)(2 * tid) / 128.0f;
        float invf = 1.0f / powf(10000.0f, expo);
        float a = (float)b * invf;
        g_cos[b*64 + tid] = cosf(a);
        g_sin[b*64 + tid] = sinf(a);
    }
    if (b >= 1024 && b < 1152) {
        int w = (b - 1024)*256 + tid;
        int n = w >> 14, rem = w & 16383;
        int t = rem >> 10, q = rem & 1023;
        const int* mr = mask + ((size_t)n << 20) + q*1024 + t*64;
        uint32_t lo = 0, hi = 0;
        #pragma unroll
        for (int i4 = 0; i4 < 8; i4++) {
            int4 m = reinterpret_cast<const int4*>(mr)[i4];
            lo |= (uint32_t)(m.x != 0) << (i4*4 + 0);
            lo |= (uint32_t)(m.y != 0) << (i4*4 + 1);
            lo |= (uint32_t)(m.z != 0) << (i4*4 + 2);
            lo |= (uint32_t)(m.w != 0) << (i4*4 + 3);
        }
        #pragma unroll
        for (int i4 = 8; i4 < 16; i4++) {
            int4 m = reinterpret_cast<const int4*>(mr)[i4];
            hi |= (uint32_t)(m.x != 0) << ((i4-8)*4 + 0);
            hi |= (uint32_t)(m.y != 0) << ((i4-8)*4 + 1);
            hi |= (uint32_t)(m.z != 0) << ((i4-8)*4 + 2);
            hi |= (uint32_t)(m.w != 0) << ((i4-8)*4 + 3);
        }
        g_mp[(n*16 + t)*1024 + q] = make_uint2(lo, hi);
    }
}

// ---------------------------------------------------------------------------
// K1: fused RoPE + per-head projection (32768x128x128). grid (256, 3)
// ---------------------------------------------------------------------------
__device__ __forceinline__ void ldgf(float4 v[4], const float* __restrict__ g,
                                     int stride, int tid) {
    #pragma unroll
    for (int t = 0; t < 2; t++) {
        int i = tid + t*256;
        int r = i >> 2, k8 = (i & 3) << 3;
        v[2*t]   = *reinterpret_cast<const float4*>(g + (size_t)r*stride + k8);
        v[2*t+1] = *reinterpret_cast<const float4*>(g + (size_t)r*stride + k8 + 4);
    }
}
__device__ __forceinline__ void stsf(__half* S, const float4 v[4], int tid) {
    #pragma unroll
    for (int t = 0; t < 2; t++) {
        int i = tid + t*256;
        int r = i >> 2, k8 = (i & 3) << 3;
        *reinterpret_cast<uint4*>(S + r*ST + k8) = pack8(v[2*t], v[2*t+1]);
    }
}
__device__ __forceinline__ void ldg_rope(float4 v[4], const float* __restrict__ X,
                                         int base, int k0, int tid) {
    #pragma unroll
    for (int t = 0; t < 2; t++) {
        int i = tid + t*256;
        int r = i >> 2, k8 = (i & 3) << 3;
        int rg = base + r;
        int l = (rg >> 4) & 1023;
        const float* xr = X + (size_t)rg*128;
        #pragma unroll
        for (int hlf = 0; hlf < 2; hlf++) {
            int dd = k0 + k8 + hlf*4;
            float4 f = *reinterpret_cast<const float4*>(xr + dd);
            float4 m = *reinterpret_cast<const float4*>(xr + 124 - dd);
            float4 c = *reinterpret_cast<const float4*>(g_cos + l*64 + (dd & 63));
            float4 s = *reinterpret_cast<const float4*>(g_sin + l*64 + (dd & 63));
            v[2*t+hlf] = make_float4(f.x*c.x + m.w*s.x, f.y*c.y + m.z*s.y,
                                     f.z*c.z + m.y*s.z, f.w*c.w + m.x*s.w);
        }
    }
}

__global__ __launch_bounds__(256, 2) void proj_kernel(
    const float* __restrict__ qin, const float* __restrict__ kin,
    const float* __restrict__ vin,
    const float* __restrict__ Wq, const float* __restrict__ Wk,
    const float* __restrict__ Wv)
{
    __shared__ __half sm[4*TILE_H];
    __half *A0 = sm, *A1 = sm + TILE_H, *B0 = sm + 2*TILE_H, *B1 = sm + 3*TILE_H;
    uint32_t smb = smem_u32(sm);
    int tid = threadIdx.x;
    int lane = tid & 31, wid = tid >> 5;
    int tr = lane >> 2, tk = lane & 3;
    int wr = wid >> 2, wc = wid & 3;
    int tensor = blockIdx.y;
    const float* X = (tensor == 0) ? qin : (tensor == 1) ? kin : vin;
    const float* W = (tensor == 0) ? Wq  : (tensor == 1) ? Wk  : Wv;
    __half* OUT    = (tensor == 0) ? g_q : (tensor == 1) ? g_k : g_v;
    bool rope = (tensor < 2);
    float osc = (tensor == 0) ? QSCALE : 1.0f;
    int base = blockIdx.x * 128;

    float d[4][4][4] = {};
    float4 va[4], vb[4];

    if (rope) ldg_rope(va, X, base, 0, tid);
    else      ldgf(va, X + (size_t)base*128, 128, tid);
    ldgf(vb, W, 128, tid);
    stsf(A0, va, tid); stsf(B0, vb, tid);
    __syncthreads();

    #pragma unroll
    for (int t = 0; t < 4; t++) {
        if (t < 3) {
            int k0 = (t+1)*32;
            if (rope) ldg_rope(va, X, base, k0, tid);
            else      ldgf(va, X + (size_t)base*128 + k0, 128, tid);
            ldgf(vb, W + k0, 128, tid);
        }
        uint32_t Asa = smb + (uint32_t)(((t & 1) ? TILE_H : 0))*2;
        uint32_t Bsa = smb + (uint32_t)((2 + (t & 1))*TILE_H)*2;
        mma_k16_ldsm<ST>(Asa, Bsa, 0, d, lane, wr, wc);
        mma_k16_ldsm<ST>(Asa, Bsa, 1, d, lane, wr, wc);
        if (t < 3) {
            stsf((t & 1) ? A0 : A1, va, tid);
            stsf((t & 1) ? B0 : B1, vb, tid);
        }
        __syncthreads();
    }

    #pragma unroll
    for (int mt = 0; mt < 4; mt++) {
        int rg = base + wr*64 + mt*16 + tr;
        #pragma unroll
        for (int nt = 0; nt < 4; nt++) {
            int col = wc*32 + nt*8 + tk*2;
            *reinterpret_cast<uint32_t*>(&OUT[(size_t)rg*128 + col]) =
                packh2(d[mt][nt][0]*osc, d[mt][nt][1]*osc);
            *reinterpret_cast<uint32_t*>(&OUT[(size_t)(rg+8)*128 + col]) =
                packh2(d[mt][nt][2]*osc, d[mt][nt][3]*osc);
        }
    }
}

// ---------------------------------------------------------------------------
// K2: FLASH attention (no-max softmax). grid (8, 32), 256 threads, 2 CTAs/SM.
// ---------------------------------------------------------------------------
#define FST 136
#define QTILE (128*FST)
#define KTILE (64*FST)
#define FLASH_BYTES ((QTILE + 4*KTILE)*2)   // 104448

__device__ __forceinline__ void cp_ftileQ(uint32_t sb, const __half* __restrict__ g,
                                          int stride, int tid) {
    #pragma unroll
    for (int j = 0; j < 8; j++) {
        int id = tid + j*256;
        int r = id >> 4, c = id & 15;
        cp16(sb + (r*FST + c*8)*2, g + (size_t)r*stride + c*8);
    }
}
__device__ __forceinline__ void cp_ftile64(uint32_t sb, const __half* __restrict__ g,
                                           int stride, int tid) {
    #pragma unroll
    for (int j = 0; j < 4; j++) {
        int id = tid + j*256;
        int r = id >> 4, c = id & 15;
        cp16(sb + (r*FST + c*8)*2, g + (size_t)r*stride + c*8);
    }
}

__global__ __launch_bounds__(256, 2) void flash_kernel()
{
    extern __shared__ __half dsm[];
    int tid = threadIdx.x;
    int lane = tid & 31, wid = tid >> 5;
    int tr = lane >> 2, tk = lane & 3;
    int w16 = wid * 16;
    int nh = blockIdx.y;
    int n = nh >> 4, h = nh & 15;
    int q0 = blockIdx.x * 128;

    uint32_t qb = smem_u32(dsm);
    uint32_t kb[2] = {(uint32_t)(qb + QTILE*2), (uint32_t)(qb + (QTILE + KTILE)*2)};
    uint32_t vb[2] = {(uint32_t)(qb + (QTILE + 2*KTILE)*2),
                      (uint32_t)(qb + (QTILE + 3*KTILE)*2)};

    const __half* Kg = g_k + ((size_t)n*LL*HH + h)*DD;
    const __half* Vg = g_v + ((size_t)n*LL*HH + h)*DD;

    cp_ftileQ(qb, g_q + ((size_t)(n*LL + q0)*HH + h)*DD, HH*DD, tid);
    cp_ftile64(kb[0], Kg, HH*DD, tid);
    CP_COMMIT();
    cp_ftile64(vb[0], Vg, HH*DD, tid);
    CP_COMMIT();
    cp_ftile64(kb[1], Kg + (size_t)64*HH*DD, HH*DD, tid);
    CP_COMMIT();

    uint32_t a_off = ((uint32_t)((w16 + (lane & 15))*FST + ((lane >> 4) << 3))) * 2;
    int b_row = ((lane >> 4) << 3) + (lane & 7);
    int b_koff = ((lane >> 3) & 1) << 3;
    int v_row = (((lane >> 3) & 1) << 3) + (lane & 7);
    int v_coff = (lane >> 4) << 3;

    float o[16][4] = {};
    float l0 = 0.0f, l1 = 0.0f;

    int q_r0 = q0 + w16 + tr;
    int tk2 = tk*2;

    for (int t = 0; t < 16; t++) {
        CP_WAIT2();
        __syncthreads();

        float d[8][4] = {};
        uint32_t kbase = kb[t & 1];
        #pragma unroll
        for (int ks = 0; ks < 8; ks++) {
            uint32_t a[4];
            ldsm_x4(a, qb + a_off + ks*32);
            #pragma unroll
            for (int ntp = 0; ntp < 4; ntp++) {
                uint32_t b[4];
                ldsm_x4(b, kbase + ((uint32_t)((ntp*16 + b_row)*FST + ks*16 + b_koff))*2);
                mma16(d[2*ntp],   a, b);
                mma16(d[2*ntp+1], a, b + 2);
            }
        }

        uint2 wq0 = g_mp[(n*16 + t)*1024 + q_r0];
        uint2 wq1 = g_mp[(n*16 + t)*1024 + q_r0 + 8];
        uint32_t l0b = wq0.x >> tk2, h0b = wq0.y >> tk2;
        uint32_t l1b = wq1.x >> tk2, h1b = wq1.y >> tk2;

        float rs0 = 0.0f, rs1 = 0.0f;
        #pragma unroll
        for (int nt = 0; nt < 8; nt++) {
            uint32_t b0 = ((nt < 4) ? l0b : h0b) >> ((nt & 3)*8);
            uint32_t b1 = ((nt < 4) ? l1b : h1b) >> ((nt & 3)*8);
            float e0 = ex2f(d[nt][0]);
            float e1 = ex2f(d[nt][1]);
            float e2 = ex2f(d[nt][2]);
            float e3 = ex2f(d[nt][3]);
            d[nt][0] = (b0 & 1u) ? e0 : 0.0f;
            d[nt][1] = (b0 & 2u) ? e1 : 0.0f;
            d[nt][2] = (b1 & 1u) ? e2 : 0.0f;
            d[nt][3] = (b1 & 2u) ? e3 : 0.0f;
            rs0 += d[nt][0] + d[nt][1];
            rs1 += d[nt][2] + d[nt][3];
        }
        l0 += rs0;
        l1 += rs1;

        CP_WAIT1();
        __syncthreads();
        if (t < 15) cp_ftile64(vb[(t+1) & 1], Vg + (size_t)(t+1)*64*HH*DD, HH*DD, tid);
        CP_COMMIT();
        if (t < 14) cp_ftile64(kb[t & 1], Kg + (size_t)(t+2)*64*HH*DD, HH*DD, tid);
        CP_COMMIT();

        uint32_t vbase = vb[t & 1];
        #pragma unroll
        for (int ks = 0; ks < 4; ks++) {
            uint32_t a[4];
            a[0] = packh2(d[2*ks][0],   d[2*ks][1]);
            a[1] = packh2(d[2*ks][2],   d[2*ks][3]);
            a[2] = packh2(d[2*ks+1][0], d[2*ks+1][1]);
            a[3] = packh2(d[2*ks+1][2], d[2*ks+1][3]);
            #pragma unroll
            for (int ntp = 0; ntp < 8; ntp++) {
                uint32_t b[4];
                ldsm_x4t(b, vbase + ((uint32_t)((ks*16 + v_row)*FST + ntp*16 + v_coff))*2);
                mma16(o[2*ntp],   a, b);
                mma16(o[2*ntp+1], a, b + 2);
            }
        }
    }

    l0 += __shfl_xor_sync(0xffffffffu, l0, 1);
    l0 += __shfl_xor_sync(0xffffffffu, l0, 2);
    l1 += __shfl_xor_sync(0xffffffffu, l1, 1);
    l1 += __shfl_xor_sync(0xffffffffu, l1, 2);
    float inv0 = 1.0f / l0, inv1 = 1.0f / l1;

    #pragma unroll
    for (int nt = 0; nt < 16; nt++) {
        int col = nt*8 + tk*2;
        *reinterpret_cast<uint32_t*>(&g_o[((size_t)(n*LL + q_r0)*HH + h)*DD + col]) =
            packh2(o[nt][0]*inv0, o[nt][1]*inv0);
        *reinterpret_cast<uint32_t*>(&g_o[((size_t)(n*LL + q_r0 + 8)*HH + h)*DD + col]) =
            packh2(o[nt][2]*inv1, o[nt][3]*inv1);
    }
}

// ---------------------------------------------------------------------------
// K3: out = X @ Wo^T + bo. BK=64, 32 iters, 3-stage ring. grid (16, 16).
// 128 threads, 4 warps in 2x2, warp tile 64x64.
// ---------------------------------------------------------------------------
__global__ __launch_bounds__(128, 2) void out_kernel(
    const float* __restrict__ bo, float* __restrict__ out)
{
    extern __shared__ __half dsm[];
    int tid = threadIdx.x;
    int lane = tid & 31, wid = tid >> 5;
    int tr = lane >> 2, tk = lane & 3;
    int wr = wid >> 1, wc = wid & 1;
    int c0 = blockIdx.x * 128;
    int r0 = blockIdx.y * 128;
    const __half* Ag = g_o + (size_t)r0*2048;
    const __half* Bg = g_woh + (size_t)c0*2048;

    float d[4][8][4] = {};
    uint32_t sb = smem_u32(dsm);

    cp_tile64(sb,                  Ag,      2048, tid);
    cp_tile64(sb + TILE64_H*2,     Bg,      2048, tid);
    CP_COMMIT();
    cp_tile64(sb + 2*TILE64_H*2,   Ag + 64, 2048, tid);
    cp_tile64(sb + 3*TILE64_H*2,   Bg + 64, 2048, tid);
    CP_COMMIT();

    int ar = lane & 15, ak = (lane >> 4) << 3;
    int brw = ((lane >> 4) << 3) + (lane & 7);
    int bk = ((lane >> 3) & 1) << 3;

    for (int t = 0; t < 32; t++) {
        CP_WAIT1();
        __syncthreads();
        if (t + 2 < 32) {
            int s = (t + 2) % STAGES;
            cp_tile64(sb + (uint32_t)(2*s)*TILE64_H*2,   Ag + (t+2)*64, 2048, tid);
            cp_tile64(sb + (uint32_t)(2*s+1)*TILE64_H*2, Bg + (t+2)*64, 2048, tid);
        }
        CP_COMMIT();
        uint32_t Asa = sb + (uint32_t)((t % STAGES)*2*TILE64_H)*2;
        uint32_t Bsa = Asa + TILE64_H*2;
        #pragma unroll
        for (int ks = 0; ks < 4; ks++) {
            uint32_t a[4][4];
            #pragma unroll
            for (int mt = 0; mt < 4; mt++)
                ldsm_x4(a[mt], Asa + (uint32_t)((wr*64 + mt*16 + ar)*ST2 + ks*16 + ak)*2);
            #pragma unroll
            for (int g = 0; g < 4; g++) {
                uint32_t b[4];
                ldsm_x4(b, Bsa + (uint32_t)((wc*64 + g*16 + brw)*ST2 + ks*16 + bk)*2);
                #pragma unroll
                for (int mt = 0; mt < 4; mt++) {
                    mma16(d[mt][2*g],   a[mt], b);
                    mma16(d[mt][2*g+1], a[mt], b + 2);
                }
            }
        }
    }

    #pragma unroll
    for (int mt = 0; mt < 4; mt++) {
        int r = r0 + wr*64 + mt*16 + tr;
        #pragma unroll
        for (int nt = 0; nt < 8; nt++) {
            int col = c0 + wc*64 + nt*8 + tk*2;
            float2 bb = *reinterpret_cast<const float2*>(&bo[col]);
            *reinterpret_cast<float2*>(&out[(size_t)r*2048 + col]) =
                make_float2(d[mt][nt][0] + bb.x, d[mt][nt][1] + bb.y);
            *reinterpret_cast<float2*>(&out[(size_t)(r+8)*2048 + col]) =
                make_float2(d[mt][nt][2] + bb.x, d[mt][nt][3] + bb.y);
        }
    }
}

// ---------------------------------------------------------------------------
// Launch: values, keys, queries, mask, Wv, Wk, Wq, Wo, bo
// ---------------------------------------------------------------------------
extern "C" void kernel_launch(void* const* d_in, const int* in_sizes, int n_in,
                              void* d_out, int out_size)
{
    const float* values  = (const float*)d_in[0];
    const float* keys    = (const float*)d_in[1];
    const float* queries = (const float*)d_in[2];
    const int*   mask    = (const int*)  d_in[3];
    const float* Wv      = (const float*)d_in[4];
    const float* Wk      = (const float*)d_in[5];
    const float* Wq      = (const float*)d_in[6];
    const float* Wo      = (const float*)d_in[7];
    const float* bo      = (const float*)d_in[8];
    float* out = (float*)d_out;

    cudaFuncSetAttribute(flash_kernel, cudaFuncAttributeMaxDynamicSharedMemorySize, FLASH_BYTES);
    cudaFuncSetAttribute(out_kernel,   cudaFuncAttributeMaxDynamicSharedMemorySize, OUT_BYTES);

    prelude_kernel<<<2048, 256>>>(Wo, mask);
    proj_kernel<<<dim3(256, 3), 256>>>(queries, keys, values, Wq, Wk, Wv);
    flash_kernel<<<dim3(8, 32), 256, FLASH_BYTES>>>();
    out_kernel<<<dim3(16, 16), 128, OUT_BYTES>>>(bo, out);
}